// round 1
// baseline (speedup 1.0000x reference)
#include <cuda_runtime.h>

#define T_STEPS 365
#define NCELL   65536
#define HID     64
#define BD      224   // threads per block (7 warps)

// smem layout (floats): Whh[12288] | ig4[192*4] | bo2[64*2] | h[BD*64]
#define SMEM_FLOATS (12288 + 768 + 128 + BD * 64)
#define SMEM_BYTES  (SMEM_FLOATS * 4)

__device__ __forceinline__ unsigned long long ffma2(unsigned long long a,
                                                    unsigned long long b,
                                                    unsigned long long c) {
    unsigned long long d;
    asm("fma.rn.f32x2 %0, %1, %2, %3;" : "=l"(d) : "l"(a), "l"(b), "l"(c));
    return d;
}
__device__ __forceinline__ unsigned long long pack2(float lo, float hi) {
    unsigned long long d;
    asm("mov.b64 %0, {%1, %2};" : "=l"(d) : "f"(lo), "f"(hi));
    return d;
}
__device__ __forceinline__ float2 unpack2(unsigned long long v) {
    float2 r;
    asm("mov.b64 {%0, %1}, %2;" : "=f"(r.x), "=f"(r.y) : "l"(v));
    return r;
}
__device__ __forceinline__ float frcp(float x) {
    float r;
    asm("rcp.approx.f32 %0, %1;" : "=f"(r) : "f"(x));
    return r;
}
__device__ __forceinline__ float sigmoid_f(float x) {
    return frcp(1.0f + __expf(-x));
}
__device__ __forceinline__ float tanh_f(float x) {
    // tanh(x) = 2*sigmoid(2x) - 1  (ex2/rcp approx path, ~1e-6 rel err)
    return fmaf(2.0f, frcp(1.0f + __expf(-2.0f * x)), -1.0f);
}

extern __shared__ float smem[];

__global__ __launch_bounds__(BD, 2)
void gru_scan_kernel(const float* __restrict__ pr,   // (T, N)
                     const float* __restrict__ te,   // (T, N)
                     const float* __restrict__ wih,  // (192, 2)
                     const float* __restrict__ whh,  // (192, 64)
                     const float* __restrict__ bias, // (192)
                     const float* __restrict__ bias_n, // (64)
                     const float* __restrict__ outw,  // (1, 64)
                     const float* __restrict__ outb,  // (1)
                     const float* __restrict__ init_h,// (64)
                     float* __restrict__ out)         // smb (T*N) then final_h (N*64)
{
    float*  Wsh = smem;                                  // 12288 floats
    float4* ig4 = (float4*)(smem + 12288);               // 192 float4: {wih0, wih1, bias, 0}
    float2* bo2 = (float2*)(smem + 12288 + 768);         // 64 float2: {bias_n, outw}
    float*  hsm = smem + 12288 + 768 + 128;              // [64][BD]

    const int tid = threadIdx.x;

    // cooperative loads of the small shared operands
    {
        const float4* src = (const float4*)whh;
        float4* dst = (float4*)Wsh;
        #pragma unroll 4
        for (int j = tid; j < 12288 / 4; j += BD) dst[j] = src[j];
        for (int j = tid; j < 192; j += BD)
            ig4[j] = make_float4(wih[2 * j], wih[2 * j + 1], bias[j], 0.0f);
        for (int j = tid; j < 64; j += BD)
            bo2[j] = make_float2(bias_n[j], outw[j]);
    }
    __syncthreads();

    const int cell = blockIdx.x * BD + tid;
    if (cell >= NCELL) return;   // only after the cooperative load + sync

    // initialize hidden state (smem scalar copy + packed register snapshot)
    unsigned long long hp[32];
    #pragma unroll
    for (int q = 0; q < 32; q++) {
        float h0 = init_h[2 * q];
        float h1 = init_h[2 * q + 1];
        hsm[(2 * q) * BD + tid]     = h0;
        hsm[(2 * q + 1) * BD + tid] = h1;
        hp[q] = pack2(h0, h1);
    }

    const float ob = outb[0];

    for (int t = 0; t < T_STEPS; t++) {
        const float xp = pr[(size_t)t * NCELL + cell];
        const float xt = te[(size_t)t * NCELL + cell];
        float y = ob;

        #pragma unroll 2
        for (int i = 0; i < HID; i++) {
            // W rows for this hidden unit (r: i, z: i+64, n: i+128), broadcast LDS.128
            const ulonglong2* wr = (const ulonglong2*)(Wsh + i * 64);
            const ulonglong2* wz = (const ulonglong2*)(Wsh + (i + 64) * 64);
            const ulonglong2* wn = (const ulonglong2*)(Wsh + (i + 128) * 64);

            unsigned long long ar = 0ull, az = 0ull, an = 0ull;  // (0.f,0.f) packed
            #pragma unroll
            for (int m = 0; m < 16; m++) {
                ulonglong2 a = wr[m];
                ar = ffma2(a.x, hp[2 * m], ar);
                ar = ffma2(a.y, hp[2 * m + 1], ar);
                ulonglong2 b = wz[m];
                az = ffma2(b.x, hp[2 * m], az);
                az = ffma2(b.y, hp[2 * m + 1], az);
                ulonglong2 c = wn[m];
                an = ffma2(c.x, hp[2 * m], an);
                an = ffma2(c.y, hp[2 * m + 1], an);
            }
            float2 arf = unpack2(ar), azf = unpack2(az), anf = unpack2(an);
            const float hr = arf.x + arf.y;
            const float hz = azf.x + azf.y;
            const float hn = anf.x + anf.y;

            const float4 gr = ig4[i];
            const float4 gz = ig4[64 + i];
            const float4 gn = ig4[128 + i];
            const float ir_ = fmaf(xp, gr.x, fmaf(xt, gr.y, gr.z));
            const float iz_ = fmaf(xp, gz.x, fmaf(xt, gz.y, gz.z));
            const float in_ = fmaf(xp, gn.x, fmaf(xt, gn.y, gn.z));

            const float2 bo = bo2[i];
            const float r  = sigmoid_f(ir_ + hr);
            const float z  = sigmoid_f(iz_ + hz);
            const float nv = tanh_f(fmaf(r, hn + bo.x, in_));

            const float hold = hsm[i * BD + tid];     // pre-update value (snapshot in hp)
            const float hv   = fmaf(z, hold - nv, nv); // n + z*(h - n)
            hsm[i * BD + tid] = hv;
            y = fmaf(bo.y, hv, y);
        }

        out[(size_t)t * NCELL + cell] = y;

        // refresh packed register snapshot for next step
        #pragma unroll
        for (int q = 0; q < 32; q++)
            hp[q] = pack2(hsm[(2 * q) * BD + tid], hsm[(2 * q + 1) * BD + tid]);
    }

    // final hidden state: (N, 64), contiguous per cell -> 16x STG.128
    float4* fo = (float4*)(out + (size_t)T_STEPS * NCELL + (size_t)cell * HID);
    #pragma unroll
    for (int q = 0; q < 16; q++) {
        fo[q] = make_float4(hsm[(4 * q) * BD + tid],
                            hsm[(4 * q + 1) * BD + tid],
                            hsm[(4 * q + 2) * BD + tid],
                            hsm[(4 * q + 3) * BD + tid]);
    }
}

extern "C" void kernel_launch(void* const* d_in, const int* in_sizes, int n_in,
                              void* d_out, int out_size) {
    const float* pr     = (const float*)d_in[0];  // precipitation (T,H,W)
    const float* te     = (const float*)d_in[1];  // temperature  (T,H,W)
    const float* wih    = (const float*)d_in[2];  // (192,2)
    const float* whh    = (const float*)d_in[3];  // (192,64)
    const float* bias   = (const float*)d_in[4];  // (192)
    const float* bias_n = (const float*)d_in[5];  // (64)
    const float* outw   = (const float*)d_in[6];  // (1,64)
    const float* outb   = (const float*)d_in[7];  // (1)
    const float* init_h = (const float*)d_in[8];  // (64)
    float* out = (float*)d_out;

    cudaFuncSetAttribute(gru_scan_kernel,
                         cudaFuncAttributeMaxDynamicSharedMemorySize, SMEM_BYTES);

    const int grid = (NCELL + BD - 1) / BD;  // 293 blocks, 2 resident per SM -> 1 wave
    gru_scan_kernel<<<grid, BD, SMEM_BYTES>>>(pr, te, wih, whh, bias, bias_n,
                                              outw, outb, init_h, out);
}

// round 4
// speedup vs baseline: 3.2624x; 3.2624x over previous
#include <cuda_runtime.h>
#include <cstdint>

#define T_STEPS 365
#define NCELL   65536
#define BD      224      // 7 warps * 32
#define CPB     112      // cells per block (7 warps * 16)
#define GRID    586      // ceil(65536/112)
#define KSTR    72       // padded k stride (bf16 elems) for conflict-free ldmatrix

#define OFF_WHI 0
#define OFF_WLO (192*KSTR*2)           // 27648
#define OFF_PK  (2*192*KSTR*2)         // 55296
#define SMEM_BYTES (OFF_PK + 32*6*16)  // 58368

// ---------- helpers ----------
__device__ __forceinline__ uint32_t smem_u32(const void* p) {
    uint32_t r;
    asm("{ .reg .u64 t; cvta.to.shared.u64 t, %1; cvt.u32.u64 %0, t; }" : "=r"(r) : "l"(p));
    return r;
}
// pack two f32 -> bf16x2, lower half = first arg
__device__ __forceinline__ uint32_t pk2(float lo, float hi) {
    uint32_t d;
    asm("cvt.rn.bf16x2.f32 %0, %1, %2;" : "=r"(d) : "f"(hi), "f"(lo));
    return d;
}
__device__ __forceinline__ float bl(uint32_t u) { return __uint_as_float(u << 16); }
__device__ __forceinline__ float bh(uint32_t u) { return __uint_as_float(u & 0xFFFF0000u); }

__device__ __forceinline__ void mma16816(float* c, const uint32_t* a, const uint32_t* b) {
    asm volatile(
        "mma.sync.aligned.m16n8k16.row.col.f32.bf16.bf16.f32 "
        "{%0,%1,%2,%3}, {%4,%5,%6,%7}, {%8,%9}, {%0,%1,%2,%3};"
        : "+f"(c[0]), "+f"(c[1]), "+f"(c[2]), "+f"(c[3])
        : "r"(a[0]), "r"(a[1]), "r"(a[2]), "r"(a[3]), "r"(b[0]), "r"(b[1]));
}
__device__ __forceinline__ void ldsm4(uint32_t* r, uint32_t addr) {
    asm volatile("ldmatrix.sync.aligned.m8n8.x4.shared.b16 {%0,%1,%2,%3}, [%4];"
                 : "=r"(r[0]), "=r"(r[1]), "=r"(r[2]), "=r"(r[3]) : "r"(addr));
}
// reset gate only: sigmoid via tanh.approx (1 MUFU, error heavily damped downstream)
__device__ __forceinline__ float sigt(float x) {
    float r;
    asm("tanh.approx.f32 %0, %1;" : "=f"(r) : "f"(0.5f * x));
    return fmaf(0.5f, r, 0.5f);
}
// accurate sigmoid: 1/(1+2^(-x*log2e))  (2 MUFU, err ~1e-6)
__device__ __forceinline__ float siga(float x) {
    float e, r;
    asm("ex2.approx.f32 %0, %1;" : "=f"(e) : "f"(-1.4426950408889634f * x));
    asm("rcp.approx.f32 %0, %1;" : "=f"(r) : "f"(e + 1.0f));
    return r;
}
// accurate tanh: 1 - 2/(e^{2x}+1)  (2 MUFU, err ~1e-6)
__device__ __forceinline__ float tanha(float x) {
    float e, r;
    asm("ex2.approx.f32 %0, %1;" : "=f"(e) : "f"(2.8853900817779268f * x));
    asm("rcp.approx.f32 %0, %1;" : "=f"(r) : "f"(e + 1.0f));
    return fmaf(-2.0f, r, 1.0f);
}

extern __shared__ char smc[];

__global__ __launch_bounds__(BD, 2)
void gru_mma_kernel(const float* __restrict__ pr, const float* __restrict__ te,
                    const float* __restrict__ wih, const float* __restrict__ whh,
                    const float* __restrict__ bias, const float* __restrict__ bias_n,
                    const float* __restrict__ outw, const float* __restrict__ outb,
                    const float* __restrict__ init_h, float* __restrict__ out) {
    const int tid = threadIdx.x;

    // ---- W_hh hi/lo bf16 tiles in smem: [n=192][k padded to KSTR] ----
    for (int p = tid; p < 192 * 32; p += BD) {
        int n = p >> 5, kp = p & 31;
        float w0 = whh[n * 64 + 2 * kp], w1 = whh[n * 64 + 2 * kp + 1];
        uint32_t hi = pk2(w0, w1);
        uint32_t lo = pk2(w0 - bl(hi), w1 - bh(hi));
        uint32_t off = (uint32_t)(n * KSTR + 2 * kp) * 2;
        *(uint32_t*)(smc + OFF_WHI + off) = hi;
        *(uint32_t*)(smc + OFF_WLO + off) = lo;
    }
    // ---- packed scalar params per unit-pair p: units {2p, 2p+1} ----
    if (tid < 32) {
        int p = tid, a = 2 * p, b = a + 1;
        float4* pk = (float4*)(smc + OFF_PK) + p * 6;
        pk[0] = make_float4(wih[2*a], wih[2*a+1], bias[a], wih[2*b]);
        pk[1] = make_float4(wih[2*b+1], bias[b], wih[2*(64+a)], wih[2*(64+a)+1]);
        pk[2] = make_float4(bias[64+a], wih[2*(64+b)], wih[2*(64+b)+1], bias[64+b]);
        pk[3] = make_float4(wih[2*(128+a)], wih[2*(128+a)+1], bias[128+a], wih[2*(128+b)]);
        pk[4] = make_float4(wih[2*(128+b)+1], bias[128+b], bias_n[a], bias_n[b]);
        pk[5] = make_float4(outw[a], outw[b], 0.0f, 0.0f);
    }
    __syncthreads();

    const int warp = tid >> 5, lane = tid & 31;
    const int gid = lane >> 2, q = lane & 3;
    const int cellbase = blockIdx.x * CPB + warp * 16;
    const int c0 = cellbase + gid, c8 = c0 + 8;
    const int c0c = min(c0, NCELL - 1), c8c = min(c8, NCELL - 1);
    const bool v0 = c0 < NCELL, v8 = c8 < NCELL;

    const uint32_t sb = smem_u32(smc);
    const uint32_t lmoff = (uint32_t)((lane & 7) * KSTR + (lane >> 3) * 8) * 2;
    const float4* pkbase = (const float4*)(smc + OFF_PK);

    // ---- fp32 hidden state: hs0/hs8[2j+{0,1}] = h[row gid / gid+8][unit 8j+2q+{0,1}]
    float hs0[16], hs8[16];
    #pragma unroll
    for (int j = 0; j < 8; j++) {
        const int u = 8 * j + 2 * q;
        hs0[2*j]   = init_h[u];     hs0[2*j+1] = init_h[u + 1];
        hs8[2*j]   = init_h[u];     hs8[2*j+1] = init_h[u + 1];
    }
    const float ob = outb[0];

    for (int t = 0; t < T_STEPS; t++) {
        const size_t base = (size_t)t * NCELL;
        const float xp0 = pr[base + c0c], xp8 = pr[base + c8c];
        const float xt0 = te[base + c0c], xt8 = te[base + c8c];

        // ---- pack frozen A fragments (bf16 hi/lo) from fp32 state ----
        // reg order per kt: 0 = row g / k-lo, 1 = row g+8 / k-lo, 2 = row g / k-hi, 3 = row g+8 / k-hi
        uint32_t AH[4][4], AL[4][4];
        #pragma unroll
        for (int kt = 0; kt < 4; kt++) {
            #pragma unroll
            for (int hh = 0; hh < 2; hh++) {
                const int j = 2 * kt + hh;
                uint32_t h0 = pk2(hs0[2*j], hs0[2*j+1]);
                AH[kt][2*hh] = h0;
                AL[kt][2*hh] = pk2(hs0[2*j] - bl(h0), hs0[2*j+1] - bh(h0));
                uint32_t h8 = pk2(hs8[2*j], hs8[2*j+1]);
                AH[kt][2*hh+1] = h8;
                AL[kt][2*hh+1] = pk2(hs8[2*j] - bl(h8), hs8[2*j+1] - bh(h8));
            }
        }

        float y0 = 0.0f, y8 = 0.0f;

        #pragma unroll
        for (int j = 0; j < 8; j++) {
            float c[3][4];
            #pragma unroll
            for (int g = 0; g < 3; g++) {
                uint32_t bhf[8], blf[8];
                const uint32_t nb = (uint32_t)(g * 64 + 8 * j) * (KSTR * 2);
                ldsm4(bhf,     sb + OFF_WHI + nb + lmoff);
                ldsm4(bhf + 4, sb + OFF_WHI + nb + lmoff + 64);
                ldsm4(blf,     sb + OFF_WLO + nb + lmoff);
                ldsm4(blf + 4, sb + OFF_WLO + nb + lmoff + 64);
                c[g][0] = c[g][1] = c[g][2] = c[g][3] = 0.0f;
                #pragma unroll
                for (int k2 = 0; k2 < 4; k2++) {
                    mma16816(c[g], AH[k2], bhf + 2 * k2);
                    mma16816(c[g], AL[k2], bhf + 2 * k2);
                    mma16816(c[g], AH[k2], blf + 2 * k2);
                }
            }
            // ---- epilogue: units a=8j+2q, b=a+1, rows gid and gid+8 ----
            const float4* pp = pkbase + (4 * j + q) * 6;
            const float4 k0 = pp[0], k1 = pp[1], k2 = pp[2], k3 = pp[3], k4 = pp[4], k5 = pp[5];

            const float ra0 = sigt(fmaf(xp0, k0.x, fmaf(xt0, k0.y, k0.z)) + c[0][0]);
            const float rb0 = sigt(fmaf(xp0, k0.w, fmaf(xt0, k1.x, k1.y)) + c[0][1]);
            const float ra8 = sigt(fmaf(xp8, k0.x, fmaf(xt8, k0.y, k0.z)) + c[0][2]);
            const float rb8 = sigt(fmaf(xp8, k0.w, fmaf(xt8, k1.x, k1.y)) + c[0][3]);

            const float za0 = siga(fmaf(xp0, k1.z, fmaf(xt0, k1.w, k2.x)) + c[1][0]);
            const float zb0 = siga(fmaf(xp0, k2.y, fmaf(xt0, k2.z, k2.w)) + c[1][1]);
            const float za8 = siga(fmaf(xp8, k1.z, fmaf(xt8, k1.w, k2.x)) + c[1][2]);
            const float zb8 = siga(fmaf(xp8, k2.y, fmaf(xt8, k2.z, k2.w)) + c[1][3]);

            const float na0 = tanha(fmaf(ra0, c[2][0] + k4.z, fmaf(xp0, k3.x, fmaf(xt0, k3.y, k3.z))));
            const float nb0 = tanha(fmaf(rb0, c[2][1] + k4.w, fmaf(xp0, k3.w, fmaf(xt0, k4.x, k4.y))));
            const float na8 = tanha(fmaf(ra8, c[2][2] + k4.z, fmaf(xp8, k3.x, fmaf(xt8, k3.y, k3.z))));
            const float nb8 = tanha(fmaf(rb8, c[2][3] + k4.w, fmaf(xp8, k3.w, fmaf(xt8, k4.x, k4.y))));

            const float nha0 = fmaf(za0, hs0[2*j]   - na0, na0);
            const float nhb0 = fmaf(zb0, hs0[2*j+1] - nb0, nb0);
            const float nha8 = fmaf(za8, hs8[2*j]   - na8, na8);
            const float nhb8 = fmaf(zb8, hs8[2*j+1] - nb8, nb8);

            hs0[2*j] = nha0; hs0[2*j+1] = nhb0;
            hs8[2*j] = nha8; hs8[2*j+1] = nhb8;

            y0 = fmaf(k5.x, nha0, fmaf(k5.y, nhb0, y0));
            y8 = fmaf(k5.x, nha8, fmaf(k5.y, nhb8, y8));
        }

        // quad reduce y (lanes within a quad differ only in q)
        y0 += __shfl_xor_sync(0xffffffff, y0, 1);
        y0 += __shfl_xor_sync(0xffffffff, y0, 2);
        y8 += __shfl_xor_sync(0xffffffff, y8, 1);
        y8 += __shfl_xor_sync(0xffffffff, y8, 2);
        if (q == 0) {
            if (v0) out[base + c0] = y0 + ob;
            if (v8) out[base + c8] = y8 + ob;
        }
    }

    // ---- final hidden state (N, 64), fp32 state written directly ----
    float* fo = out + (size_t)T_STEPS * NCELL;
    #pragma unroll
    for (int j = 0; j < 8; j++) {
        const int u = 8 * j + 2 * q;
        if (v0) *(float2*)(fo + (size_t)c0 * 64 + u) = make_float2(hs0[2*j], hs0[2*j+1]);
        if (v8) *(float2*)(fo + (size_t)c8 * 64 + u) = make_float2(hs8[2*j], hs8[2*j+1]);
    }
}

extern "C" void kernel_launch(void* const* d_in, const int* in_sizes, int n_in,
                              void* d_out, int out_size) {
    const float* pr     = (const float*)d_in[0];
    const float* te     = (const float*)d_in[1];
    const float* wih    = (const float*)d_in[2];
    const float* whh    = (const float*)d_in[3];
    const float* bias   = (const float*)d_in[4];
    const float* bias_n = (const float*)d_in[5];
    const float* outw   = (const float*)d_in[6];
    const float* outb   = (const float*)d_in[7];
    const float* init_h = (const float*)d_in[8];
    float* out = (float*)d_out;

    cudaFuncSetAttribute(gru_mma_kernel,
                         cudaFuncAttributeMaxDynamicSharedMemorySize, SMEM_BYTES);

    gru_mma_kernel<<<GRID, BD, SMEM_BYTES>>>(pr, te, wih, whh, bias, bias_n,
                                             outw, outb, init_h, out);
}